// round 4
// baseline (speedup 1.0000x reference)
#include <cuda_runtime.h>
#include <cuda_bf16.h>
#include <cuda_fp8.h>
#include <cstdint>

#define MDIM 16384
#define KDIM 2048
#define NDIM 2048

// Scratch: dequantized activations (bf16) and weights (bf16).
__device__ __nv_bfloat16 g_xd[(size_t)MDIM * KDIM];   // 64 MiB
__device__ __nv_bfloat16 g_wd[(size_t)NDIM * KDIM];   // 8 MiB

// ---------------------------------------------------------------------------
// Kernel 1: activation block quantize (128-elem blocks along K), then
// dequantize to bf16 (exact: fp8 value * power-of-2 scale is exact in bf16).
// One warp per 128-element block.
// ---------------------------------------------------------------------------
__global__ void quant_x_kernel(const float* __restrict__ x) {
    int b = blockIdx.x * (blockDim.x >> 5) + (threadIdx.x >> 5);
    const int nblocks = MDIM * (KDIM / 128);
    if (b >= nblocks) return;
    int lane = threadIdx.x & 31;
    const float* px = x + (size_t)b * 128;
    __nv_bfloat16* pd = g_xd + (size_t)b * 128;

    float v[4];
    float amax = 0.f;
#pragma unroll
    for (int i = 0; i < 4; i++) {
        float f = __bfloat162float(__float2bfloat16(px[lane + 32 * i]));
        v[i] = f;
        amax = fmaxf(amax, fabsf(f));
    }
#pragma unroll
    for (int o = 16; o; o >>= 1)
        amax = fmaxf(amax, __shfl_xor_sync(0xffffffffu, amax, o));

    float s = fmaxf(amax, 1e-4f) / 448.0f;
    // round scale UP to a power of two: s2 = 2^ceil(log2(s)), exact via frexp
    int e;
    float m = frexpf(s, &e);            // s = m * 2^e, m in [0.5, 1)
    float s2 = (m == 0.5f) ? ldexpf(1.f, e - 1) : ldexpf(1.f, e);
    float inv = 1.f / s2;               // exact (power of two)

#pragma unroll
    for (int i = 0; i < 4; i++) {
        __nv_fp8_storage_t q = __nv_cvt_float_to_fp8(v[i] * inv, __NV_SATFINITE, __NV_E4M3);
        __half_raw hr = __nv_cvt_fp8_to_halfraw(q, __NV_E4M3);
        float deq = __half2float(*(__half*)&hr) * s2;
        pd[lane + 32 * i] = __float2bfloat16(deq);
    }
}

// ---------------------------------------------------------------------------
// Kernel 2: weight fp8 cast + per-(128,128)-block scale, dequantized to bf16.
// ---------------------------------------------------------------------------
__global__ void quant_w_kernel(const float* __restrict__ w, const float* __restrict__ sinv) {
    int idx = blockIdx.x * blockDim.x + threadIdx.x;
    if (idx >= NDIM * KDIM) return;
    int n = idx / KDIM;
    int k = idx - n * KDIM;
    __nv_fp8_storage_t q = __nv_cvt_float_to_fp8(w[idx], __NV_SATFINITE, __NV_E4M3);
    __half_raw hr = __nv_cvt_fp8_to_halfraw(q, __NV_E4M3);
    float f = __half2float(*(__half*)&hr);
    f *= sinv[(n >> 7) * (KDIM >> 7) + (k >> 7)];
    g_wd[idx] = __float2bfloat16(f);
}

// ---------------------------------------------------------------------------
// Kernel 3: bf16 NT GEMM, C[m,n] = sum_k A[m,k]*B[n,k], fp32 accum.
// OUTPUT IS FLOAT32: values are rounded to bf16 then stored as fp32 to match
// the reference's bf16 output materialized in a float32 buffer.
// CTA tile 128x128, BK=32, 8 warps (4x2), warp tile 32x64, mma.m16n8k16.
// 3-stage cp.async pipeline, padded smem, explicit per-thread fragment LDS.
// ---------------------------------------------------------------------------
constexpr int BM = 128, BN = 128, BK = 32;
constexpr int STAGES = 3;
constexpr int ROWLEN = BK + 8;                       // 40 elems (pad => conflict-free)
constexpr int STAGE_ELEMS = (BM + BN) * ROWLEN;      // 10240 bf16 per stage

__device__ __forceinline__ void cp_async16(uint32_t dst, const void* src) {
    asm volatile("cp.async.cg.shared.global [%0], [%1], 16;\n" :: "r"(dst), "l"(src));
}
__device__ __forceinline__ void cp_commit() {
    asm volatile("cp.async.commit_group;\n" ::: "memory");
}
template <int N>
__device__ __forceinline__ void cp_wait() {
    asm volatile("cp.async.wait_group %0;\n" :: "n"(N) : "memory");
}
__device__ __forceinline__ void mma_bf16(float* c, const uint32_t* a, const uint32_t* b) {
    asm volatile("mma.sync.aligned.m16n8k16.row.col.f32.bf16.bf16.f32 "
                 "{%0,%1,%2,%3}, {%4,%5,%6,%7}, {%8,%9}, {%0,%1,%2,%3};\n"
                 : "+f"(c[0]), "+f"(c[1]), "+f"(c[2]), "+f"(c[3])
                 : "r"(a[0]), "r"(a[1]), "r"(a[2]), "r"(a[3]), "r"(b[0]), "r"(b[1]));
}

__device__ __forceinline__ float bf16_round(float f) {
    return __bfloat162float(__float2bfloat16_rn(f));
}

__global__ __launch_bounds__(256) void gemm_kernel(float* __restrict__ C) {
    extern __shared__ __nv_bfloat16 sm[];
    const int tid = threadIdx.x;
    const int lane = tid & 31;
    const int wid = tid >> 5;
    const int bm = blockIdx.y * BM;
    const int bn = blockIdx.x * BN;
    const int wm = (wid & 3) * 32;    // warp row offset in CTA tile
    const int wn = (wid >> 2) * 64;   // warp col offset

    const uint32_t sm_u32 = (uint32_t)__cvta_generic_to_shared(sm);

    const __nv_bfloat16* A = g_xd;
    const __nv_bfloat16* B = g_wd;

    float acc[2][8][4];
#pragma unroll
    for (int i = 0; i < 2; i++)
#pragma unroll
        for (int j = 0; j < 8; j++)
#pragma unroll
            for (int l = 0; l < 4; l++) acc[i][j][l] = 0.f;

    // ---- stage loader: A rows 0..127 (m), B rows 0..127 (n), BK=32 per row ----
    auto load_stage = [&](int s, int k0) {
        uint32_t baseA = sm_u32 + (uint32_t)(s * STAGE_ELEMS) * 2u;
        uint32_t baseB = baseA + (uint32_t)(BM * ROWLEN) * 2u;
#pragma unroll
        for (int i = 0; i < 2; i++) {
            int c = tid + 256 * i;          // 0..511
            int row = c >> 2, cc = c & 3;   // 4 chunks per row
            const __nv_bfloat16* srcA = A + (size_t)(bm + row) * KDIM + k0 + cc * 8;
            cp_async16(baseA + (uint32_t)(row * ROWLEN + cc * 8) * 2u, srcA);
        }
#pragma unroll
        for (int i = 0; i < 2; i++) {
            int c = tid + 256 * i;
            int row = c >> 2, cc = c & 3;
            const __nv_bfloat16* srcB = B + (size_t)(bn + row) * KDIM + k0 + cc * 8;
            cp_async16(baseB + (uint32_t)(row * ROWLEN + cc * 8) * 2u, srcB);
        }
    };

    constexpr int NK = KDIM / BK;   // 64
    load_stage(0, 0);
    cp_commit();
    load_stage(1, BK);
    cp_commit();

    const int gr = lane >> 2;         // 0..7 : fragment "groupID"
    const int gc = (lane & 3) * 2;    // 0,2,4,6 : fragment column pair

    for (int kt = 0; kt < NK; kt++) {
        if (kt + 2 < NK) {
            load_stage((kt + 2) % STAGES, (kt + 2) * BK);
            cp_commit();
        }
        int rem = NK - 1 - kt;
        if (rem >= 2)      cp_wait<2>();
        else if (rem == 1) cp_wait<1>();
        else               cp_wait<0>();
        __syncthreads();

        const __nv_bfloat16* sA = sm + (kt % STAGES) * STAGE_ELEMS;
        const __nv_bfloat16* sB = sA + BM * ROWLEN;

#pragma unroll
        for (int ks = 0; ks < 2; ks++) {        // two k16 steps in BK=32
            const int k0 = ks * 16;
            uint32_t a[2][4];
#pragma unroll
            for (int mt = 0; mt < 2; mt++) {
                int r = wm + mt * 16 + gr;
                a[mt][0] = *(const uint32_t*)(sA + r * ROWLEN + k0 + gc);
                a[mt][1] = *(const uint32_t*)(sA + (r + 8) * ROWLEN + k0 + gc);
                a[mt][2] = *(const uint32_t*)(sA + r * ROWLEN + k0 + 8 + gc);
                a[mt][3] = *(const uint32_t*)(sA + (r + 8) * ROWLEN + k0 + 8 + gc);
            }
#pragma unroll
            for (int p = 0; p < 4; p++) {
#pragma unroll
                for (int h = 0; h < 2; h++) {
                    int n = wn + p * 16 + h * 8 + gr;
                    uint32_t b[2];
                    b[0] = *(const uint32_t*)(sB + n * ROWLEN + k0 + gc);
                    b[1] = *(const uint32_t*)(sB + n * ROWLEN + k0 + 8 + gc);
#pragma unroll
                    for (int mt = 0; mt < 2; mt++)
                        mma_bf16(acc[mt][2 * p + h], a[mt], b);
                }
            }
        }
        __syncthreads();
    }

    // ---- epilogue: round to bf16, store as FLOAT32 (vectorized float2) ----
    const int gid = lane >> 2, tig = lane & 3;
#pragma unroll
    for (int mt = 0; mt < 2; mt++) {
#pragma unroll
        for (int nt = 0; nt < 8; nt++) {
            int row = bm + wm + mt * 16 + gid;
            int col = bn + wn + nt * 8 + tig * 2;
            float2 v01 = make_float2(bf16_round(acc[mt][nt][0]), bf16_round(acc[mt][nt][1]));
            *(float2*)&C[(size_t)row * NDIM + col] = v01;
            float2 v23 = make_float2(bf16_round(acc[mt][nt][2]), bf16_round(acc[mt][nt][3]));
            *(float2*)&C[(size_t)(row + 8) * NDIM + col] = v23;
        }
    }
}

// ---------------------------------------------------------------------------
// Inputs identified BY ELEMENT COUNT (no ordering assumption):
//   x: 33554432, weight: 4194304, sinv: 256.
// ---------------------------------------------------------------------------
extern "C" void kernel_launch(void* const* d_in, const int* in_sizes, int n_in,
                              void* d_out, int out_size) {
    const float* x    = nullptr;
    const float* w    = nullptr;
    const float* sinv = nullptr;
    for (int i = 0; i < n_in; i++) {
        long long sz = in_sizes[i];
        if (sz == (long long)MDIM * KDIM)      x    = (const float*)d_in[i];
        else if (sz == (long long)NDIM * KDIM) w    = (const float*)d_in[i];
        else                                   sinv = (const float*)d_in[i];
    }
    if (!x)    x    = (const float*)d_in[0];
    if (!w)    w    = (const float*)d_in[1];
    if (!sinv) sinv = (const float*)d_in[2];

    float* out = (float*)d_out;

    // 1) activation quantize+dequant (one warp per 128-block)
    {
        int nblocks = MDIM * (KDIM / 128);      // 262144
        int ctas = nblocks / 8;                 // 8 warps per CTA
        quant_x_kernel<<<ctas, 256>>>(x);
    }
    // 2) weight dequant
    {
        int total = NDIM * KDIM;
        quant_w_kernel<<<(total + 255) / 256, 256>>>(w, sinv);
    }
    // 3) bf16 GEMM, fp32 output (bf16-rounded values)
    {
        int smem_bytes = STAGES * STAGE_ELEMS * 2;   // 61440
        cudaFuncSetAttribute(gemm_kernel, cudaFuncAttributeMaxDynamicSharedMemorySize, smem_bytes);
        dim3 grid(NDIM / BN, MDIM / BM);             // (16, 128)
        gemm_kernel<<<grid, 256, smem_bytes>>>(out);
    }
}

// round 6
// speedup vs baseline: 1.0056x; 1.0056x over previous
#include <cuda_runtime.h>
#include <cuda_bf16.h>
#include <cuda_fp8.h>
#include <cstdint>

#define MDIM 16384
#define KDIM 2048
#define NDIM 2048
#define KB   (KDIM / 128)   // 16 quant blocks along K

// Scratch: fp8 operands + per-block float scales for activations.
__device__ uint8_t g_x8[(size_t)MDIM * KDIM];   // 32 MiB
__device__ uint8_t g_w8[(size_t)NDIM * KDIM];   // 4 MiB
__device__ float   g_sa[(size_t)MDIM * KB];     // 1 MiB

__device__ __forceinline__ float bf16_round(float f) {
    return __bfloat162float(__float2bfloat16(f));
}

// ---------------------------------------------------------------------------
// Kernel 1: activation quantize. One warp per 128-block. fp8 + float scale.
// ---------------------------------------------------------------------------
__global__ void quant_x_kernel(const float* __restrict__ x) {
    int b = blockIdx.x * (blockDim.x >> 5) + (threadIdx.x >> 5);
    if (b >= MDIM * KB) return;
    int lane = threadIdx.x & 31;

    float4 v4 = ((const float4*)x)[(size_t)b * 32 + lane];
    float v[4] = { v4.x, v4.y, v4.z, v4.w };
    float amax = 0.f;
#pragma unroll
    for (int i = 0; i < 4; i++) {
        v[i] = bf16_round(v[i]);               // reference casts x to bf16 first
        amax = fmaxf(amax, fabsf(v[i]));
    }
#pragma unroll
    for (int o = 16; o; o >>= 1)
        amax = fmaxf(amax, __shfl_xor_sync(0xffffffffu, amax, o));

    float s = fmaxf(amax, 1e-4f) / 448.0f;
    int e; float m = frexpf(s, &e);            // s = m*2^e, m in [0.5,1)
    float s2 = (m == 0.5f) ? ldexpf(1.f, e - 1) : ldexpf(1.f, e);  // 2^ceil(log2 s)
    float inv = 1.f / s2;                      // exact (power of two)

    uint32_t pack = 0;
#pragma unroll
    for (int i = 0; i < 4; i++) {
        uint32_t q = __nv_cvt_float_to_fp8(v[i] * inv, __NV_SATFINITE, __NV_E4M3);
        pack |= q << (8 * i);
    }
    ((uint32_t*)g_x8)[(size_t)b * 32 + lane] = pack;
    if (lane == 0) g_sa[b] = s2;
}

// ---------------------------------------------------------------------------
// Kernel 2: weight fp8 cast (block scale applied in GEMM epilogue path).
// ---------------------------------------------------------------------------
__global__ void quant_w_kernel(const float* __restrict__ w) {
    int i = blockIdx.x * blockDim.x + threadIdx.x;      // float4 index
    if (i >= NDIM * KDIM / 4) return;
    float4 w4 = ((const float4*)w)[i];
    float v[4] = { w4.x, w4.y, w4.z, w4.w };
    uint32_t pack = 0;
#pragma unroll
    for (int j = 0; j < 4; j++) {
        uint32_t q = __nv_cvt_float_to_fp8(v[j], __NV_SATFINITE, __NV_E4M3);
        pack |= q << (8 * j);
    }
    ((uint32_t*)g_w8)[i] = pack;
}

// ---------------------------------------------------------------------------
// Kernel 3: FP8 NT GEMM via mma.sync.m16n8k32.e4m3 with two-level accumulation.
// CTA tile 128x128, BK=128 (= one quant block), 8 warps (4x2), warp tile 32x64.
// Per k-block: zero partial acc, 4 k32 mma steps, master += part * (sa*sw).
// 3-stage cp.async pipeline, padded smem rows (128+16 B), raw LDS fragments.
// ---------------------------------------------------------------------------
constexpr int BM = 128, BN = 128, BK = 128;
constexpr int STAGES = 3;
constexpr int ROWB = BK + 16;                        // 144 bytes per smem row
constexpr int STAGE_BYTES = (BM + BN) * ROWB;        // 36864
constexpr int SMEM_TOTAL = STAGES * STAGE_BYTES;     // 110592

__device__ __forceinline__ void cp_async16(uint32_t dst, const void* src) {
    asm volatile("cp.async.cg.shared.global [%0], [%1], 16;\n" :: "r"(dst), "l"(src));
}
__device__ __forceinline__ void cp_commit() {
    asm volatile("cp.async.commit_group;\n" ::: "memory");
}
template <int N>
__device__ __forceinline__ void cp_wait() {
    asm volatile("cp.async.wait_group %0;\n" :: "n"(N) : "memory");
}
__device__ __forceinline__ void mma_fp8(float* c, const uint32_t* a, const uint32_t* b) {
    asm volatile("mma.sync.aligned.m16n8k32.row.col.f32.e4m3.e4m3.f32 "
                 "{%0,%1,%2,%3}, {%4,%5,%6,%7}, {%8,%9}, {%0,%1,%2,%3};\n"
                 : "+f"(c[0]), "+f"(c[1]), "+f"(c[2]), "+f"(c[3])
                 : "r"(a[0]), "r"(a[1]), "r"(a[2]), "r"(a[3]), "r"(b[0]), "r"(b[1]));
}

__global__ __launch_bounds__(256, 1) void gemm_kernel(float* __restrict__ C,
                                                      const float* __restrict__ sinv) {
    extern __shared__ uint8_t sm[];
    const int tid = threadIdx.x;
    const int lane = tid & 31;
    const int wid = tid >> 5;
    const int bm = blockIdx.y * BM;
    const int bn = blockIdx.x * BN;
    const int nb = blockIdx.x;            // n-block (BN==128)
    const int wm = (wid & 3) * 32;
    const int wn = (wid >> 2) * 64;

    const uint32_t sm_u32 = (uint32_t)__cvta_generic_to_shared(sm);
    const uint8_t* A = g_x8;
    const uint8_t* B = g_w8;

    float master[2][8][4];
#pragma unroll
    for (int i = 0; i < 2; i++)
#pragma unroll
        for (int j = 0; j < 8; j++)
#pragma unroll
            for (int l = 0; l < 4; l++) master[i][j][l] = 0.f;

    // ---- stage loader: A rows (m), B rows (n), 128 fp8 per row, 8x16B ----
    auto load_stage = [&](int s, int kb) {
        uint32_t baseA = sm_u32 + (uint32_t)(s * STAGE_BYTES);
        uint32_t baseB = baseA + (uint32_t)(BM * ROWB);
#pragma unroll
        for (int i = 0; i < 4; i++) {
            int c = tid + 256 * i;          // 0..1023
            int row = c >> 3, cc = c & 7;
            cp_async16(baseA + (uint32_t)(row * ROWB + cc * 16),
                       A + (size_t)(bm + row) * KDIM + kb * 128 + cc * 16);
        }
#pragma unroll
        for (int i = 0; i < 4; i++) {
            int c = tid + 256 * i;
            int row = c >> 3, cc = c & 7;
            cp_async16(baseB + (uint32_t)(row * ROWB + cc * 16),
                       B + (size_t)(bn + row) * KDIM + kb * 128 + cc * 16);
        }
    };

    load_stage(0, 0);
    cp_commit();
    load_stage(1, 1);
    cp_commit();

    const int gr = lane >> 2;          // fragment row-in-tile 0..7
    const int gb = (lane & 3) * 4;     // fragment byte offset 0,4,8,12

    for (int kb = 0; kb < KB; kb++) {
        if (kb + 2 < KB) {
            load_stage((kb + 2) % STAGES, kb + 2);
            cp_commit();
        }
        int rem = KB - 1 - kb;
        if (rem >= 2)      cp_wait<2>();
        else if (rem == 1) cp_wait<1>();
        else               cp_wait<0>();
        __syncthreads();

        const uint8_t* sA = sm + (kb % STAGES) * STAGE_BYTES;
        const uint8_t* sB = sA + BM * ROWB;

        float part[2][8][4];
#pragma unroll
        for (int i = 0; i < 2; i++)
#pragma unroll
            for (int j = 0; j < 8; j++)
#pragma unroll
                for (int l = 0; l < 4; l++) part[i][j][l] = 0.f;

#pragma unroll
        for (int ks = 0; ks < 4; ks++) {          // four k32 steps in BK=128
            const int k0 = ks * 32;
            uint32_t a[2][4];
#pragma unroll
            for (int mt = 0; mt < 2; mt++) {
                int r = wm + mt * 16 + gr;
                a[mt][0] = *(const uint32_t*)(sA + r * ROWB + k0 + gb);
                a[mt][1] = *(const uint32_t*)(sA + (r + 8) * ROWB + k0 + gb);
                a[mt][2] = *(const uint32_t*)(sA + r * ROWB + k0 + 16 + gb);
                a[mt][3] = *(const uint32_t*)(sA + (r + 8) * ROWB + k0 + 16 + gb);
            }
#pragma unroll
            for (int p = 0; p < 4; p++) {
#pragma unroll
                for (int h = 0; h < 2; h++) {
                    int n = wn + p * 16 + h * 8 + gr;
                    uint32_t b[2];
                    b[0] = *(const uint32_t*)(sB + n * ROWB + k0 + gb);
                    b[1] = *(const uint32_t*)(sB + n * ROWB + k0 + 16 + gb);
#pragma unroll
                    for (int mt = 0; mt < 2; mt++)
                        mma_fp8(part[mt][2 * p + h], a[mt], b);
                }
            }
        }

        // ---- fold k-block scales into master accumulator ----
        float swk = __ldg(&sinv[nb * KB + kb]);
#pragma unroll
        for (int mt = 0; mt < 2; mt++) {
            int r0 = bm + wm + mt * 16 + gr;
            float f0 = __ldg(&g_sa[(size_t)r0 * KB + kb]) * swk;        // rows c0,c1
            float f1 = __ldg(&g_sa[(size_t)(r0 + 8) * KB + kb]) * swk;  // rows c2,c3
#pragma unroll
            for (int nt = 0; nt < 8; nt++) {
                master[mt][nt][0] += part[mt][nt][0] * f0;
                master[mt][nt][1] += part[mt][nt][1] * f0;
                master[mt][nt][2] += part[mt][nt][2] * f1;
                master[mt][nt][3] += part[mt][nt][3] * f1;
            }
        }
        __syncthreads();
    }

    // ---- epilogue: round to bf16, store as fp32 (float2) ----
    const int gid = lane >> 2, tig = lane & 3;
#pragma unroll
    for (int mt = 0; mt < 2; mt++) {
#pragma unroll
        for (int nt = 0; nt < 8; nt++) {
            int row = bm + wm + mt * 16 + gid;
            int col = bn + wn + nt * 8 + tig * 2;
            float2 v01 = make_float2(bf16_round(master[mt][nt][0]), bf16_round(master[mt][nt][1]));
            *(float2*)&C[(size_t)row * NDIM + col] = v01;
            float2 v23 = make_float2(bf16_round(master[mt][nt][2]), bf16_round(master[mt][nt][3]));
            *(float2*)&C[(size_t)(row + 8) * NDIM + col] = v23;
        }
    }
}

// ---------------------------------------------------------------------------
// Inputs identified BY ELEMENT COUNT: x 33554432, weight 4194304, sinv 256.
// ---------------------------------------------------------------------------
extern "C" void kernel_launch(void* const* d_in, const int* in_sizes, int n_in,
                              void* d_out, int out_size) {
    const float* x = nullptr; const float* w = nullptr; const float* sinv = nullptr;
    for (int i = 0; i < n_in; i++) {
        long long sz = in_sizes[i];
        if (sz == (long long)MDIM * KDIM)      x    = (const float*)d_in[i];
        else if (sz == (long long)NDIM * KDIM) w    = (const float*)d_in[i];
        else                                   sinv = (const float*)d_in[i];
    }
    if (!x)    x    = (const float*)d_in[0];
    if (!w)    w    = (const float*)d_in[1];
    if (!sinv) sinv = (const float*)d_in[2];
    float* out = (float*)d_out;

    { // 1) activation quantize -> fp8 + float scales
        int nblocks = MDIM * KB;                       // 262144
        quant_x_kernel<<<nblocks / 8, 256>>>(x);
    }
    { // 2) weight -> fp8
        int words = NDIM * KDIM / 4;
        quant_w_kernel<<<words / 256, 256>>>(w);
    }
    { // 3) fp8 GEMM with per-block rescale
        cudaFuncSetAttribute(gemm_kernel, cudaFuncAttributeMaxDynamicSharedMemorySize, SMEM_TOTAL);
        dim3 grid(NDIM / BN, MDIM / BM);               // (16, 128)
        gemm_kernel<<<grid, 256, SMEM_TOTAL>>>(out, sinv);
    }
}

// round 7
// speedup vs baseline: 1.0674x; 1.0614x over previous
#include <cuda_runtime.h>
#include <cuda_bf16.h>
#include <cuda_fp8.h>
#include <cstdint>

#define MDIM 16384
#define KDIM 2048
#define NDIM 2048
#define KB   (KDIM / 128)   // 16 quant blocks along K

// Scratch: fp8 operands + per-block float scales for activations.
__device__ uint8_t g_x8[(size_t)MDIM * KDIM];   // 32 MiB
__device__ uint8_t g_w8[(size_t)NDIM * KDIM];   // 4 MiB
__device__ float   g_sa[(size_t)MDIM * KB];     // 1 MiB

__device__ __forceinline__ float bf16_round(float f) {
    return __bfloat162float(__float2bfloat16(f));
}

// ---------------------------------------------------------------------------
// Kernel 1: activation quantize. One warp per 128-block. fp8 + float scale.
// ---------------------------------------------------------------------------
__global__ void quant_x_kernel(const float* __restrict__ x) {
    int b = blockIdx.x * (blockDim.x >> 5) + (threadIdx.x >> 5);
    if (b >= MDIM * KB) return;
    int lane = threadIdx.x & 31;

    float4 v4 = ((const float4*)x)[(size_t)b * 32 + lane];
    float v[4] = { v4.x, v4.y, v4.z, v4.w };
    float amax = 0.f;
#pragma unroll
    for (int i = 0; i < 4; i++) {
        v[i] = bf16_round(v[i]);               // reference casts x to bf16 first
        amax = fmaxf(amax, fabsf(v[i]));
    }
#pragma unroll
    for (int o = 16; o; o >>= 1)
        amax = fmaxf(amax, __shfl_xor_sync(0xffffffffu, amax, o));

    float s = fmaxf(amax, 1e-4f) / 448.0f;
    int e; float m = frexpf(s, &e);            // s = m*2^e, m in [0.5,1)
    float s2 = (m == 0.5f) ? ldexpf(1.f, e - 1) : ldexpf(1.f, e);  // 2^ceil(log2 s)
    float inv = 1.f / s2;                      // exact (power of two)

    __nv_fp8x2_storage_t lo = __nv_cvt_float2_to_fp8x2(
        make_float2(v[0] * inv, v[1] * inv), __NV_SATFINITE, __NV_E4M3);
    __nv_fp8x2_storage_t hi = __nv_cvt_float2_to_fp8x2(
        make_float2(v[2] * inv, v[3] * inv), __NV_SATFINITE, __NV_E4M3);
    ((uint32_t*)g_x8)[(size_t)b * 32 + lane] = (uint32_t)lo | ((uint32_t)hi << 16);
    if (lane == 0) g_sa[b] = s2;
}

// ---------------------------------------------------------------------------
// Kernel 2: weight fp8 cast (block scale applied in GEMM).
// ---------------------------------------------------------------------------
__global__ void quant_w_kernel(const float* __restrict__ w) {
    int i = blockIdx.x * blockDim.x + threadIdx.x;      // float4 index
    if (i >= NDIM * KDIM / 4) return;
    float4 w4 = ((const float4*)w)[i];
    __nv_fp8x2_storage_t lo = __nv_cvt_float2_to_fp8x2(
        make_float2(w4.x, w4.y), __NV_SATFINITE, __NV_E4M3);
    __nv_fp8x2_storage_t hi = __nv_cvt_float2_to_fp8x2(
        make_float2(w4.z, w4.w), __NV_SATFINITE, __NV_E4M3);
    ((uint32_t*)g_w8)[i] = (uint32_t)lo | ((uint32_t)hi << 16);
}

// ---------------------------------------------------------------------------
// Kernel 3: FP8 NT GEMM via mma.sync.m16n8k32.e4m3, two-level accumulation.
// CTA tile 128x128, BK=128 (one quant block), 512 threads, 16 warps (4x4),
// warp tile 32x32. 4-stage cp.async pipeline. ldmatrix.x4 fragment loads
// (fp8 m16n8k32 fragments are byte-identical to bf16 ldmatrix 16B-row tiles).
// ---------------------------------------------------------------------------
constexpr int BM = 128, BN = 128, BK = 128;
constexpr int STAGES = 4;
constexpr int ROWB = BK + 16;                        // 144 bytes/row: ldmatrix conflict-free
constexpr int STAGE_BYTES = (BM + BN) * ROWB;        // 36864
constexpr int SMEM_TOTAL = STAGES * STAGE_BYTES;     // 147456

__device__ __forceinline__ void cp_async16(uint32_t dst, const void* src) {
    asm volatile("cp.async.cg.shared.global [%0], [%1], 16;\n" :: "r"(dst), "l"(src));
}
__device__ __forceinline__ void cp_commit() {
    asm volatile("cp.async.commit_group;\n" ::: "memory");
}
template <int N>
__device__ __forceinline__ void cp_wait() {
    asm volatile("cp.async.wait_group %0;\n" :: "n"(N) : "memory");
}
__device__ __forceinline__ void ldm_x4(uint32_t& r0, uint32_t& r1, uint32_t& r2, uint32_t& r3,
                                       uint32_t addr) {
    asm volatile("ldmatrix.sync.aligned.m8n8.x4.shared.b16 {%0,%1,%2,%3}, [%4];\n"
                 : "=r"(r0), "=r"(r1), "=r"(r2), "=r"(r3) : "r"(addr));
}
__device__ __forceinline__ void mma_fp8(float* c, const uint32_t* a, const uint32_t* b) {
    asm volatile("mma.sync.aligned.m16n8k32.row.col.f32.e4m3.e4m3.f32 "
                 "{%0,%1,%2,%3}, {%4,%5,%6,%7}, {%8,%9}, {%0,%1,%2,%3};\n"
                 : "+f"(c[0]), "+f"(c[1]), "+f"(c[2]), "+f"(c[3])
                 : "r"(a[0]), "r"(a[1]), "r"(a[2]), "r"(a[3]), "r"(b[0]), "r"(b[1]));
}

__global__ __launch_bounds__(512, 1) void gemm_kernel(float* __restrict__ C,
                                                      const float* __restrict__ sinv) {
    extern __shared__ uint8_t sm[];
    const int tid = threadIdx.x;
    const int lane = tid & 31;
    const int wid = tid >> 5;                 // 0..15
    const int bm = blockIdx.y * BM;
    const int bn = blockIdx.x * BN;
    const int nb = blockIdx.x;                // n-block (BN==128)
    const int wm = (wid & 3) * 32;            // 4x4 warp grid
    const int wn = (wid >> 2) * 32;

    const uint32_t sm_u32 = (uint32_t)__cvta_generic_to_shared(sm);
    const uint8_t* A = g_x8;
    const uint8_t* B = g_w8;

    float master[2][4][4];
#pragma unroll
    for (int i = 0; i < 2; i++)
#pragma unroll
        for (int j = 0; j < 4; j++)
#pragma unroll
            for (int l = 0; l < 4; l++) master[i][j][l] = 0.f;

    // ---- stage loader: 2048 16B chunks, 512 threads x 4 iters ----
    auto load_stage = [&](int s, int kb) {
        uint32_t baseA = sm_u32 + (uint32_t)(s * STAGE_BYTES);
        uint32_t baseB = baseA + (uint32_t)(BM * ROWB);
#pragma unroll
        for (int i = 0; i < 2; i++) {
            int c = tid + 512 * i;            // A: 0..1023
            int row = c >> 3, cc = c & 7;
            cp_async16(baseA + (uint32_t)(row * ROWB + cc * 16),
                       A + (size_t)(bm + row) * KDIM + kb * 128 + cc * 16);
        }
#pragma unroll
        for (int i = 0; i < 2; i++) {
            int c = tid + 512 * i;            // B: 0..1023
            int row = c >> 3, cc = c & 7;
            cp_async16(baseB + (uint32_t)(row * ROWB + cc * 16),
                       B + (size_t)(bn + row) * KDIM + kb * 128 + cc * 16);
        }
    };

    load_stage(0, 0); cp_commit();
    load_stage(1, 1); cp_commit();
    load_stage(2, 2); cp_commit();

    // ldmatrix per-lane address components.
    // A tile (m16 x k32): lanes 0-7 rows 0-7 low16B | 8-15 rows 8-15 low |
    //                     16-23 rows 0-7 high | 24-31 rows 8-15 high
    const int la_row  = lane & 15;
    const int la_half = lane >> 4;            // 0/1 -> +0/+16 bytes
    // B tile pair (two n8 x k32 tiles): lanes 0-7 n0..7 low | 8-15 n0..7 high |
    //                                   16-23 n8..15 low | 24-31 n8..15 high
    const int lb_row  = ((lane >> 4) << 3) + (lane & 7);
    const int lb_half = (lane >> 3) & 1;

    const int gr = lane >> 2;                 // acc row-in-tile

    for (int kb = 0; kb < KB; kb++) {
        if (kb + 3 < KB) { load_stage((kb + 3) & 3, kb + 3); cp_commit(); }
        int rem = KB - 1 - kb;
        if (rem >= 3)      cp_wait<3>();
        else if (rem == 2) cp_wait<2>();
        else if (rem == 1) cp_wait<1>();
        else               cp_wait<0>();
        __syncthreads();

        const uint32_t sA = sm_u32 + (uint32_t)((kb & 3) * STAGE_BYTES);
        const uint32_t sB = sA + (uint32_t)(BM * ROWB);

        float part[2][4][4];
#pragma unroll
        for (int i = 0; i < 2; i++)
#pragma unroll
            for (int j = 0; j < 4; j++)
#pragma unroll
                for (int l = 0; l < 4; l++) part[i][j][l] = 0.f;

#pragma unroll
        for (int ks = 0; ks < 4; ks++) {      // four k32 steps in BK=128
            const int k0 = ks * 32;
            uint32_t a[2][4];
#pragma unroll
            for (int mt = 0; mt < 2; mt++) {
                uint32_t addr = sA + (uint32_t)((wm + mt * 16 + la_row) * ROWB
                                                + k0 + la_half * 16);
                ldm_x4(a[mt][0], a[mt][1], a[mt][2], a[mt][3], addr);
            }
#pragma unroll
            for (int p = 0; p < 2; p++) {
                uint32_t b[4];                // b[0..1]=tile(p,h0){b0,b1}, b[2..3]=tile(p,h1)
                uint32_t addr = sB + (uint32_t)((wn + p * 16 + lb_row) * ROWB
                                                + k0 + lb_half * 16);
                ldm_x4(b[0], b[1], b[2], b[3], addr);
#pragma unroll
                for (int mt = 0; mt < 2; mt++) {
                    mma_fp8(part[mt][2 * p + 0], a[mt], b + 0);
                    mma_fp8(part[mt][2 * p + 1], a[mt], b + 2);
                }
            }
        }

        // ---- fold k-block scales into master accumulator ----
        float swk = __ldg(&sinv[nb * KB + kb]);
#pragma unroll
        for (int mt = 0; mt < 2; mt++) {
            int r0 = bm + wm + mt * 16 + gr;
            float f0 = __ldg(&g_sa[(size_t)r0 * KB + kb]) * swk;        // rows c0,c1
            float f1 = __ldg(&g_sa[(size_t)(r0 + 8) * KB + kb]) * swk;  // rows c2,c3
#pragma unroll
            for (int nt = 0; nt < 4; nt++) {
                master[mt][nt][0] += part[mt][nt][0] * f0;
                master[mt][nt][1] += part[mt][nt][1] * f0;
                master[mt][nt][2] += part[mt][nt][2] * f1;
                master[mt][nt][3] += part[mt][nt][3] * f1;
            }
        }
        __syncthreads();
    }

    // ---- epilogue: round to bf16, store as fp32 (float2) ----
    const int gid = lane >> 2, tig = lane & 3;
#pragma unroll
    for (int mt = 0; mt < 2; mt++) {
#pragma unroll
        for (int nt = 0; nt < 4; nt++) {
            int row = bm + wm + mt * 16 + gid;
            int col = bn + wn + nt * 8 + tig * 2;
            float2 v01 = make_float2(bf16_round(master[mt][nt][0]), bf16_round(master[mt][nt][1]));
            *(float2*)&C[(size_t)row * NDIM + col] = v01;
            float2 v23 = make_float2(bf16_round(master[mt][nt][2]), bf16_round(master[mt][nt][3]));
            *(float2*)&C[(size_t)(row + 8) * NDIM + col] = v23;
        }
    }
}

// ---------------------------------------------------------------------------
// Inputs identified BY ELEMENT COUNT: x 33554432, weight 4194304, sinv 256.
// ---------------------------------------------------------------------------
extern "C" void kernel_launch(void* const* d_in, const int* in_sizes, int n_in,
                              void* d_out, int out_size) {
    const float* x = nullptr; const float* w = nullptr; const float* sinv = nullptr;
    for (int i = 0; i < n_in; i++) {
        long long sz = in_sizes[i];
        if (sz == (long long)MDIM * KDIM)      x    = (const float*)d_in[i];
        else if (sz == (long long)NDIM * KDIM) w    = (const float*)d_in[i];
        else                                   sinv = (const float*)d_in[i];
    }
    if (!x)    x    = (const float*)d_in[0];
    if (!w)    w    = (const float*)d_in[1];
    if (!sinv) sinv = (const float*)d_in[2];
    float* out = (float*)d_out;

    { // 1) activation quantize -> fp8 + float scales
        int nblocks = MDIM * KB;                       // 262144
        quant_x_kernel<<<nblocks / 8, 256>>>(x);
    }
    { // 2) weight -> fp8
        int words = NDIM * KDIM / 4;
        quant_w_kernel<<<words / 256, 256>>>(w);
    }
    { // 3) fp8 GEMM with per-block rescale
        cudaFuncSetAttribute(gemm_kernel, cudaFuncAttributeMaxDynamicSharedMemorySize, SMEM_TOTAL);
        dim3 grid(NDIM / BN, MDIM / BM);               // (16, 128)
        gemm_kernel<<<grid, 512, SMEM_TOTAL>>>(out, sinv);
    }
}

// round 8
// speedup vs baseline: 1.0947x; 1.0256x over previous
#include <cuda_runtime.h>
#include <cuda_bf16.h>
#include <cuda_fp8.h>
#include <cstdint>

#define MDIM 16384
#define KDIM 2048
#define NDIM 2048
#define KB   (KDIM / 128)   // 16 quant blocks along K

// Scratch: fp8 operands + per-block float scales for activations.
__device__ uint8_t g_x8[(size_t)MDIM * KDIM];   // 32 MiB
__device__ uint8_t g_w8[(size_t)NDIM * KDIM];   // 4 MiB
__device__ float   g_sa[(size_t)MDIM * KB];     // 1 MiB

__device__ __forceinline__ float bf16_round(float f) {
    return __bfloat162float(__float2bfloat16(f));
}

// ---------------------------------------------------------------------------
// Fused quantization kernel.
//  CTAs [0, XCTAS): activation quantize, 8 warps/CTA, 4 quant-blocks per warp
//    (MLP=4 loads in flight, 4 interleaved shfl-reduction chains).
//  CTAs [XCTAS, XCTAS+WCTAS): weight fp8 cast, grid-stride coalesced.
// ---------------------------------------------------------------------------
constexpr int XBLOCKS = MDIM * KB;            // 262144 quant blocks
constexpr int XCTAS   = XBLOCKS / (8 * 4);    // 8192
constexpr int WWORDS  = NDIM * KDIM / 4;      // 1048576 float4 words of w
constexpr int WCTAS   = 1024;                 // 256 thr * 4 words each

__global__ void quant_fused_kernel(const float* __restrict__ x,
                                   const float* __restrict__ w) {
    const int cta = blockIdx.x;
    if (cta < XCTAS) {
        // ---- activation quantize: warp handles 4 consecutive 128-blocks ----
        const int warp = cta * 8 + (threadIdx.x >> 5);
        const int lane = threadIdx.x & 31;
        const size_t b0 = (size_t)warp * 4;

        float4 v4[4];
#pragma unroll
        for (int j = 0; j < 4; j++)
            v4[j] = ((const float4*)x)[(b0 + j) * 32 + lane];

        float v[4][4], amax[4];
#pragma unroll
        for (int j = 0; j < 4; j++) {
            v[j][0] = bf16_round(v4[j].x);
            v[j][1] = bf16_round(v4[j].y);
            v[j][2] = bf16_round(v4[j].z);
            v[j][3] = bf16_round(v4[j].w);
            amax[j] = fmaxf(fmaxf(fabsf(v[j][0]), fabsf(v[j][1])),
                            fmaxf(fabsf(v[j][2]), fabsf(v[j][3])));
        }
        // 4 interleaved butterfly reductions (ILP hides shfl latency)
#pragma unroll
        for (int o = 16; o; o >>= 1) {
#pragma unroll
            for (int j = 0; j < 4; j++)
                amax[j] = fmaxf(amax[j], __shfl_xor_sync(0xffffffffu, amax[j], o));
        }

#pragma unroll
        for (int j = 0; j < 4; j++) {
            float s = fmaxf(amax[j], 1e-4f) / 448.0f;
            int e; float m = frexpf(s, &e);          // s = m*2^e, m in [0.5,1)
            float s2 = (m == 0.5f) ? ldexpf(1.f, e - 1) : ldexpf(1.f, e);
            float inv = 1.f / s2;                    // exact (power of two)
            __nv_fp8x2_storage_t lo = __nv_cvt_float2_to_fp8x2(
                make_float2(v[j][0] * inv, v[j][1] * inv), __NV_SATFINITE, __NV_E4M3);
            __nv_fp8x2_storage_t hi = __nv_cvt_float2_to_fp8x2(
                make_float2(v[j][2] * inv, v[j][3] * inv), __NV_SATFINITE, __NV_E4M3);
            ((uint32_t*)g_x8)[(b0 + j) * 32 + lane] = (uint32_t)lo | ((uint32_t)hi << 16);
            if (lane == 0) g_sa[b0 + j] = s2;
        }
    } else {
        // ---- weight fp8 cast: 4 grid-stride coalesced float4 per thread ----
        const int t = (cta - XCTAS) * 256 + threadIdx.x;   // 0..262143
#pragma unroll
        for (int j = 0; j < 4; j++) {
            int i = t + j * (WCTAS * 256);                 // coalesced stride
            float4 w4 = ((const float4*)w)[i];
            __nv_fp8x2_storage_t lo = __nv_cvt_float2_to_fp8x2(
                make_float2(w4.x, w4.y), __NV_SATFINITE, __NV_E4M3);
            __nv_fp8x2_storage_t hi = __nv_cvt_float2_to_fp8x2(
                make_float2(w4.z, w4.w), __NV_SATFINITE, __NV_E4M3);
            ((uint32_t*)g_w8)[i] = (uint32_t)lo | ((uint32_t)hi << 16);
        }
    }
}

// ---------------------------------------------------------------------------
// FP8 NT GEMM via mma.sync.m16n8k32.e4m3, two-level accumulation.
// (Unchanged from round 7 — measured at the legacy-mma hardware floor.)
// CTA tile 128x128, BK=128 (one quant block), 512 threads, 16 warps (4x4),
// warp tile 32x32. 4-stage cp.async pipeline, ldmatrix.x4 fragment loads.
// ---------------------------------------------------------------------------
constexpr int BM = 128, BN = 128, BK = 128;
constexpr int STAGES = 4;
constexpr int ROWB = BK + 16;                        // 144 bytes/row
constexpr int STAGE_BYTES = (BM + BN) * ROWB;        // 36864
constexpr int SMEM_TOTAL = STAGES * STAGE_BYTES;     // 147456

__device__ __forceinline__ void cp_async16(uint32_t dst, const void* src) {
    asm volatile("cp.async.cg.shared.global [%0], [%1], 16;\n" :: "r"(dst), "l"(src));
}
__device__ __forceinline__ void cp_commit() {
    asm volatile("cp.async.commit_group;\n" ::: "memory");
}
template <int N>
__device__ __forceinline__ void cp_wait() {
    asm volatile("cp.async.wait_group %0;\n" :: "n"(N) : "memory");
}
__device__ __forceinline__ void ldm_x4(uint32_t& r0, uint32_t& r1, uint32_t& r2, uint32_t& r3,
                                       uint32_t addr) {
    asm volatile("ldmatrix.sync.aligned.m8n8.x4.shared.b16 {%0,%1,%2,%3}, [%4];\n"
                 : "=r"(r0), "=r"(r1), "=r"(r2), "=r"(r3) : "r"(addr));
}
__device__ __forceinline__ void mma_fp8(float* c, const uint32_t* a, const uint32_t* b) {
    asm volatile("mma.sync.aligned.m16n8k32.row.col.f32.e4m3.e4m3.f32 "
                 "{%0,%1,%2,%3}, {%4,%5,%6,%7}, {%8,%9}, {%0,%1,%2,%3};\n"
                 : "+f"(c[0]), "+f"(c[1]), "+f"(c[2]), "+f"(c[3])
                 : "r"(a[0]), "r"(a[1]), "r"(a[2]), "r"(a[3]), "r"(b[0]), "r"(b[1]));
}

__global__ __launch_bounds__(512, 1) void gemm_kernel(float* __restrict__ C,
                                                      const float* __restrict__ sinv) {
    extern __shared__ uint8_t sm[];
    const int tid = threadIdx.x;
    const int lane = tid & 31;
    const int wid = tid >> 5;                 // 0..15
    const int bm = blockIdx.y * BM;
    const int bn = blockIdx.x * BN;
    const int nb = blockIdx.x;                // n-block (BN==128)
    const int wm = (wid & 3) * 32;            // 4x4 warp grid
    const int wn = (wid >> 2) * 32;

    const uint32_t sm_u32 = (uint32_t)__cvta_generic_to_shared(sm);
    const uint8_t* A = g_x8;
    const uint8_t* B = g_w8;

    float master[2][4][4];
#pragma unroll
    for (int i = 0; i < 2; i++)
#pragma unroll
        for (int j = 0; j < 4; j++)
#pragma unroll
            for (int l = 0; l < 4; l++) master[i][j][l] = 0.f;

    auto load_stage = [&](int s, int kb) {
        uint32_t baseA = sm_u32 + (uint32_t)(s * STAGE_BYTES);
        uint32_t baseB = baseA + (uint32_t)(BM * ROWB);
#pragma unroll
        for (int i = 0; i < 2; i++) {
            int c = tid + 512 * i;            // A: 0..1023
            int row = c >> 3, cc = c & 7;
            cp_async16(baseA + (uint32_t)(row * ROWB + cc * 16),
                       A + (size_t)(bm + row) * KDIM + kb * 128 + cc * 16);
        }
#pragma unroll
        for (int i = 0; i < 2; i++) {
            int c = tid + 512 * i;            // B: 0..1023
            int row = c >> 3, cc = c & 7;
            cp_async16(baseB + (uint32_t)(row * ROWB + cc * 16),
                       B + (size_t)(bn + row) * KDIM + kb * 128 + cc * 16);
        }
    };

    load_stage(0, 0); cp_commit();
    load_stage(1, 1); cp_commit();
    load_stage(2, 2); cp_commit();

    const int la_row  = lane & 15;
    const int la_half = lane >> 4;
    const int lb_row  = ((lane >> 4) << 3) + (lane & 7);
    const int lb_half = (lane >> 3) & 1;
    const int gr = lane >> 2;

    for (int kb = 0; kb < KB; kb++) {
        if (kb + 3 < KB) { load_stage((kb + 3) & 3, kb + 3); cp_commit(); }
        int rem = KB - 1 - kb;
        if (rem >= 3)      cp_wait<3>();
        else if (rem == 2) cp_wait<2>();
        else if (rem == 1) cp_wait<1>();
        else               cp_wait<0>();
        __syncthreads();

        const uint32_t sA = sm_u32 + (uint32_t)((kb & 3) * STAGE_BYTES);
        const uint32_t sB = sA + (uint32_t)(BM * ROWB);

        float part[2][4][4];
#pragma unroll
        for (int i = 0; i < 2; i++)
#pragma unroll
            for (int j = 0; j < 4; j++)
#pragma unroll
                for (int l = 0; l < 4; l++) part[i][j][l] = 0.f;

#pragma unroll
        for (int ks = 0; ks < 4; ks++) {
            const int k0 = ks * 32;
            uint32_t a[2][4];
#pragma unroll
            for (int mt = 0; mt < 2; mt++) {
                uint32_t addr = sA + (uint32_t)((wm + mt * 16 + la_row) * ROWB
                                                + k0 + la_half * 16);
                ldm_x4(a[mt][0], a[mt][1], a[mt][2], a[mt][3], addr);
            }
#pragma unroll
            for (int p = 0; p < 2; p++) {
                uint32_t b[4];
                uint32_t addr = sB + (uint32_t)((wn + p * 16 + lb_row) * ROWB
                                                + k0 + lb_half * 16);
                ldm_x4(b[0], b[1], b[2], b[3], addr);
#pragma unroll
                for (int mt = 0; mt < 2; mt++) {
                    mma_fp8(part[mt][2 * p + 0], a[mt], b + 0);
                    mma_fp8(part[mt][2 * p + 1], a[mt], b + 2);
                }
            }
        }

        float swk = __ldg(&sinv[nb * KB + kb]);
#pragma unroll
        for (int mt = 0; mt < 2; mt++) {
            int r0 = bm + wm + mt * 16 + gr;
            float f0 = __ldg(&g_sa[(size_t)r0 * KB + kb]) * swk;
            float f1 = __ldg(&g_sa[(size_t)(r0 + 8) * KB + kb]) * swk;
#pragma unroll
            for (int nt = 0; nt < 4; nt++) {
                master[mt][nt][0] += part[mt][nt][0] * f0;
                master[mt][nt][1] += part[mt][nt][1] * f0;
                master[mt][nt][2] += part[mt][nt][2] * f1;
                master[mt][nt][3] += part[mt][nt][3] * f1;
            }
        }
        __syncthreads();
    }

    const int gid = lane >> 2, tig = lane & 3;
#pragma unroll
    for (int mt = 0; mt < 2; mt++) {
#pragma unroll
        for (int nt = 0; nt < 4; nt++) {
            int row = bm + wm + mt * 16 + gid;
            int col = bn + wn + nt * 8 + tig * 2;
            float2 v01 = make_float2(bf16_round(master[mt][nt][0]), bf16_round(master[mt][nt][1]));
            *(float2*)&C[(size_t)row * NDIM + col] = v01;
            float2 v23 = make_float2(bf16_round(master[mt][nt][2]), bf16_round(master[mt][nt][3]));
            *(float2*)&C[(size_t)(row + 8) * NDIM + col] = v23;
        }
    }
}

// ---------------------------------------------------------------------------
// Inputs identified BY ELEMENT COUNT: x 33554432, weight 4194304, sinv 256.
// ---------------------------------------------------------------------------
extern "C" void kernel_launch(void* const* d_in, const int* in_sizes, int n_in,
                              void* d_out, int out_size) {
    const float* x = nullptr; const float* w = nullptr; const float* sinv = nullptr;
    for (int i = 0; i < n_in; i++) {
        long long sz = in_sizes[i];
        if (sz == (long long)MDIM * KDIM)      x    = (const float*)d_in[i];
        else if (sz == (long long)NDIM * KDIM) w    = (const float*)d_in[i];
        else                                   sinv = (const float*)d_in[i];
    }
    if (!x)    x    = (const float*)d_in[0];
    if (!w)    w    = (const float*)d_in[1];
    if (!sinv) sinv = (const float*)d_in[2];
    float* out = (float*)d_out;

    // 1) fused quantization (x + w in one launch)
    quant_fused_kernel<<<XCTAS + WCTAS, 256>>>(x, w);

    // 2) fp8 GEMM with per-block rescale
    cudaFuncSetAttribute(gemm_kernel, cudaFuncAttributeMaxDynamicSharedMemorySize, SMEM_TOTAL);
    dim3 grid(NDIM / BN, MDIM / BM);               // (16, 128)
    gemm_kernel<<<grid, 512, SMEM_TOTAL>>>(out, sinv);
}

// round 9
// speedup vs baseline: 1.1241x; 1.0268x over previous
#include <cuda_runtime.h>
#include <cuda_bf16.h>
#include <cuda_fp8.h>
#include <cstdint>

#define MDIM 16384
#define KDIM 2048
#define NDIM 2048
#define KB   (KDIM / 128)   // 16 quant blocks along K

// Scratch: fp8 operands + per-block float scales for activations.
__device__ uint8_t g_x8[(size_t)MDIM * KDIM];   // 32 MiB
__device__ uint8_t g_w8[(size_t)NDIM * KDIM];   // 4 MiB
__device__ float   g_sa[(size_t)MDIM * KB];     // 1 MiB

__device__ __forceinline__ float bf16_round(float f) {
    return __bfloat162float(__float2bfloat16(f));
}

// ---------------------------------------------------------------------------
// Fused quantization kernel (unchanged from round 8: measured ~26us).
// ---------------------------------------------------------------------------
constexpr int XBLOCKS = MDIM * KB;            // 262144 quant blocks
constexpr int XCTAS   = XBLOCKS / (8 * 4);    // 8192
constexpr int WCTAS   = 1024;

__global__ void quant_fused_kernel(const float* __restrict__ x,
                                   const float* __restrict__ w) {
    const int cta = blockIdx.x;
    if (cta < XCTAS) {
        const int warp = cta * 8 + (threadIdx.x >> 5);
        const int lane = threadIdx.x & 31;
        const size_t b0 = (size_t)warp * 4;

        float4 v4[4];
#pragma unroll
        for (int j = 0; j < 4; j++)
            v4[j] = ((const float4*)x)[(b0 + j) * 32 + lane];

        float v[4][4], amax[4];
#pragma unroll
        for (int j = 0; j < 4; j++) {
            v[j][0] = bf16_round(v4[j].x);
            v[j][1] = bf16_round(v4[j].y);
            v[j][2] = bf16_round(v4[j].z);
            v[j][3] = bf16_round(v4[j].w);
            amax[j] = fmaxf(fmaxf(fabsf(v[j][0]), fabsf(v[j][1])),
                            fmaxf(fabsf(v[j][2]), fabsf(v[j][3])));
        }
#pragma unroll
        for (int o = 16; o; o >>= 1) {
#pragma unroll
            for (int j = 0; j < 4; j++)
                amax[j] = fmaxf(amax[j], __shfl_xor_sync(0xffffffffu, amax[j], o));
        }
#pragma unroll
        for (int j = 0; j < 4; j++) {
            float s = fmaxf(amax[j], 1e-4f) / 448.0f;
            int e; float m = frexpf(s, &e);
            float s2 = (m == 0.5f) ? ldexpf(1.f, e - 1) : ldexpf(1.f, e);
            float inv = 1.f / s2;
            __nv_fp8x2_storage_t lo = __nv_cvt_float2_to_fp8x2(
                make_float2(v[j][0] * inv, v[j][1] * inv), __NV_SATFINITE, __NV_E4M3);
            __nv_fp8x2_storage_t hi = __nv_cvt_float2_to_fp8x2(
                make_float2(v[j][2] * inv, v[j][3] * inv), __NV_SATFINITE, __NV_E4M3);
            ((uint32_t*)g_x8)[(b0 + j) * 32 + lane] = (uint32_t)lo | ((uint32_t)hi << 16);
            if (lane == 0) g_sa[b0 + j] = s2;
        }
    } else {
        const int t = (cta - XCTAS) * 256 + threadIdx.x;
#pragma unroll
        for (int j = 0; j < 4; j++) {
            int i = t + j * (WCTAS * 256);
            float4 w4 = ((const float4*)w)[i];
            __nv_fp8x2_storage_t lo = __nv_cvt_float2_to_fp8x2(
                make_float2(w4.x, w4.y), __NV_SATFINITE, __NV_E4M3);
            __nv_fp8x2_storage_t hi = __nv_cvt_float2_to_fp8x2(
                make_float2(w4.z, w4.w), __NV_SATFINITE, __NV_E4M3);
            ((uint32_t*)g_w8)[i] = (uint32_t)lo | ((uint32_t)hi << 16);
        }
    }
}

// ---------------------------------------------------------------------------
// FP8 NT GEMM: CTA tile 64x128, 256 threads, 8 warps (2x4), warp tile 32x32,
// __launch_bounds__(256,2) -> 2 CTAs/SM (32 warps, 8/SMSP) to fill the tensor
// pipe (was 47% at 1 CTA/SM). 4-stage cp.async pipeline, ldmatrix.x4,
// two-level block-scale accumulation. Global address math hoisted from loop.
// ---------------------------------------------------------------------------
constexpr int BM = 64, BN = 128;
constexpr int STAGES = 4;
constexpr int ROWB = 128 + 16;                       // 144 B/row, ldmatrix conflict-free
constexpr int STAGE_BYTES = (BM + BN) * ROWB;        // 27648
constexpr int SMEM_TOTAL = STAGES * STAGE_BYTES;     // 110592

__device__ __forceinline__ void cp_async16(uint32_t dst, const void* src) {
    asm volatile("cp.async.cg.shared.global [%0], [%1], 16;\n" :: "r"(dst), "l"(src));
}
__device__ __forceinline__ void cp_commit() {
    asm volatile("cp.async.commit_group;\n" ::: "memory");
}
template <int N>
__device__ __forceinline__ void cp_wait() {
    asm volatile("cp.async.wait_group %0;\n" :: "n"(N) : "memory");
}
__device__ __forceinline__ void ldm_x4(uint32_t& r0, uint32_t& r1, uint32_t& r2, uint32_t& r3,
                                       uint32_t addr) {
    asm volatile("ldmatrix.sync.aligned.m8n8.x4.shared.b16 {%0,%1,%2,%3}, [%4];\n"
                 : "=r"(r0), "=r"(r1), "=r"(r2), "=r"(r3) : "r"(addr));
}
__device__ __forceinline__ void mma_fp8(float* c, const uint32_t* a, const uint32_t* b) {
    asm volatile("mma.sync.aligned.m16n8k32.row.col.f32.e4m3.e4m3.f32 "
                 "{%0,%1,%2,%3}, {%4,%5,%6,%7}, {%8,%9}, {%0,%1,%2,%3};\n"
                 : "+f"(c[0]), "+f"(c[1]), "+f"(c[2]), "+f"(c[3])
                 : "r"(a[0]), "r"(a[1]), "r"(a[2]), "r"(a[3]), "r"(b[0]), "r"(b[1]));
}

__global__ __launch_bounds__(256, 2) void gemm_kernel(float* __restrict__ C,
                                                      const float* __restrict__ sinv) {
    extern __shared__ uint8_t sm[];
    const int tid = threadIdx.x;
    const int lane = tid & 31;
    const int wid = tid >> 5;                 // 0..7
    const int bm = blockIdx.y * BM;
    const int bn = blockIdx.x * BN;
    const int nb = blockIdx.x;                // n-block (BN==128)
    const int wm = (wid & 1) * 32;            // 2x4 warp grid
    const int wn = (wid >> 1) * 32;

    const uint32_t sm_u32 = (uint32_t)__cvta_generic_to_shared(sm);

    // ---- precompute per-thread loader pointers (6 chunks of 16B/stage) ----
    const uint8_t* gsrc[6];
    uint32_t soff[6];
#pragma unroll
    for (int i = 0; i < 6; i++) {
        int c = tid + 256 * i;                // 0..1535
        if (c < BM * 8) {                     // A chunk
            int row = c >> 3, cc = c & 7;
            gsrc[i] = g_x8 + (size_t)(bm + row) * KDIM + cc * 16;
            soff[i] = (uint32_t)(row * ROWB + cc * 16);
        } else {                              // B chunk
            int cb = c - BM * 8;
            int row = cb >> 3, cc = cb & 7;
            gsrc[i] = g_w8 + (size_t)(bn + row) * KDIM + cc * 16;
            soff[i] = (uint32_t)(BM * ROWB + row * ROWB + cc * 16);
        }
    }
    auto load_stage = [&](int s, int kb) {
        uint32_t base = sm_u32 + (uint32_t)(s * STAGE_BYTES);
        uint32_t koff = (uint32_t)kb << 7;    // kb * 128 bytes
#pragma unroll
        for (int i = 0; i < 6; i++)
            cp_async16(base + soff[i], gsrc[i] + koff);
    };

    float master[2][4][4];
#pragma unroll
    for (int i = 0; i < 2; i++)
#pragma unroll
        for (int j = 0; j < 4; j++)
#pragma unroll
            for (int l = 0; l < 4; l++) master[i][j][l] = 0.f;

    load_stage(0, 0); cp_commit();
    load_stage(1, 1); cp_commit();
    load_stage(2, 2); cp_commit();

    const int la_row  = lane & 15;
    const int la_half = lane >> 4;
    const int lb_row  = ((lane >> 4) << 3) + (lane & 7);
    const int lb_half = (lane >> 3) & 1;
    const int gr = lane >> 2;

    // scale pointers (hoisted 64-bit math)
    const float* psa0 = g_sa + (size_t)(bm + wm + gr) * KB;         // rows c0,c1 of mt=0
    const float* psa1 = psa0 + 8 * KB;                              // +8
    const float* psa2 = psa0 + 16 * KB;                             // mt=1
    const float* psa3 = psa0 + 24 * KB;
    const float* psw  = sinv + (size_t)nb * KB;

    for (int kb = 0; kb < KB; kb++) {
        if (kb + 3 < KB) { load_stage((kb + 3) & 3, kb + 3); cp_commit(); }
        int rem = KB - 1 - kb;
        if (rem >= 3)      cp_wait<3>();
        else if (rem == 2) cp_wait<2>();
        else if (rem == 1) cp_wait<1>();
        else               cp_wait<0>();
        __syncthreads();

        const uint32_t sA = sm_u32 + (uint32_t)((kb & 3) * STAGE_BYTES);
        const uint32_t sB = sA + (uint32_t)(BM * ROWB);

        float part[2][4][4];
#pragma unroll
        for (int i = 0; i < 2; i++)
#pragma unroll
            for (int j = 0; j < 4; j++)
#pragma unroll
                for (int l = 0; l < 4; l++) part[i][j][l] = 0.f;

#pragma unroll
        for (int ks = 0; ks < 4; ks++) {      // four k32 steps in BK=128
            const int k0 = ks * 32;
            uint32_t a[2][4];
#pragma unroll
            for (int mt = 0; mt < 2; mt++) {
                uint32_t addr = sA + (uint32_t)((wm + mt * 16 + la_row) * ROWB
                                                + k0 + la_half * 16);
                ldm_x4(a[mt][0], a[mt][1], a[mt][2], a[mt][3], addr);
            }
#pragma unroll
            for (int p = 0; p < 2; p++) {
                uint32_t b[4];
                uint32_t addr = sB + (uint32_t)((wn + p * 16 + lb_row) * ROWB
                                                + k0 + lb_half * 16);
                ldm_x4(b[0], b[1], b[2], b[3], addr);
#pragma unroll
                for (int mt = 0; mt < 2; mt++) {
                    mma_fp8(part[mt][2 * p + 0], a[mt], b + 0);
                    mma_fp8(part[mt][2 * p + 1], a[mt], b + 2);
                }
            }
        }

        // ---- fold k-block scales into master ----
        float swk = __ldg(psw + kb);
        float f00 = __ldg(psa0 + kb) * swk;   // mt=0 rows c0,c1
        float f01 = __ldg(psa1 + kb) * swk;   // mt=0 rows c2,c3
        float f10 = __ldg(psa2 + kb) * swk;   // mt=1 rows c0,c1
        float f11 = __ldg(psa3 + kb) * swk;   // mt=1 rows c2,c3
#pragma unroll
        for (int nt = 0; nt < 4; nt++) {
            master[0][nt][0] += part[0][nt][0] * f00;
            master[0][nt][1] += part[0][nt][1] * f00;
            master[0][nt][2] += part[0][nt][2] * f01;
            master[0][nt][3] += part[0][nt][3] * f01;
            master[1][nt][0] += part[1][nt][0] * f10;
            master[1][nt][1] += part[1][nt][1] * f10;
            master[1][nt][2] += part[1][nt][2] * f11;
            master[1][nt][3] += part[1][nt][3] * f11;
        }
        __syncthreads();
    }

    // ---- epilogue: round to bf16, store as fp32 (float2) ----
    const int gid = lane >> 2, tig = lane & 3;
#pragma unroll
    for (int mt = 0; mt < 2; mt++) {
#pragma unroll
        for (int nt = 0; nt < 4; nt++) {
            int row = bm + wm + mt * 16 + gid;
            int col = bn + wn + nt * 8 + tig * 2;
            float2 v01 = make_float2(bf16_round(master[mt][nt][0]), bf16_round(master[mt][nt][1]));
            *(float2*)&C[(size_t)row * NDIM + col] = v01;
            float2 v23 = make_float2(bf16_round(master[mt][nt][2]), bf16_round(master[mt][nt][3]));
            *(float2*)&C[(size_t)(row + 8) * NDIM + col] = v23;
        }
    }
}

// ---------------------------------------------------------------------------
// Inputs identified BY ELEMENT COUNT: x 33554432, weight 4194304, sinv 256.
// ---------------------------------------------------------------------------
extern "C" void kernel_launch(void* const* d_in, const int* in_sizes, int n_in,
                              void* d_out, int out_size) {
    const float* x = nullptr; const float* w = nullptr; const float* sinv = nullptr;
    for (int i = 0; i < n_in; i++) {
        long long sz = in_sizes[i];
        if (sz == (long long)MDIM * KDIM)      x    = (const float*)d_in[i];
        else if (sz == (long long)NDIM * KDIM) w    = (const float*)d_in[i];
        else                                   sinv = (const float*)d_in[i];
    }
    if (!x)    x    = (const float*)d_in[0];
    if (!w)    w    = (const float*)d_in[1];
    if (!sinv) sinv = (const float*)d_in[2];
    float* out = (float*)d_out;

    // 1) fused quantization (x + w in one launch)
    quant_fused_kernel<<<XCTAS + WCTAS, 256>>>(x, w);

    // 2) fp8 GEMM with per-block rescale, 2 CTAs/SM
    cudaFuncSetAttribute(gemm_kernel, cudaFuncAttributeMaxDynamicSharedMemorySize, SMEM_TOTAL);
    dim3 grid(NDIM / BN, MDIM / BM);               // (16, 256)
    gemm_kernel<<<grid, 256, SMEM_TOTAL>>>(out, sinv);
}

// round 10
// speedup vs baseline: 1.1905x; 1.0591x over previous
#include <cuda_runtime.h>
#include <cuda_bf16.h>
#include <cuda_fp8.h>
#include <cstdint>

#define MDIM 16384
#define KDIM 2048
#define NDIM 2048
#define KB   (KDIM / 128)   // 16 quant blocks along K

// Scratch: fp8 operands + per-block float scales for activations.
__device__ uint8_t g_x8[(size_t)MDIM * KDIM];   // 32 MiB
__device__ uint8_t g_w8[(size_t)NDIM * KDIM];   // 4 MiB
__device__ float   g_sa[(size_t)MDIM * KB];     // 1 MiB

__device__ __forceinline__ float bf16_round(float f) {
    return __bfloat162float(__float2bfloat16(f));
}

// ---------------------------------------------------------------------------
// Fused quantization kernel (unchanged: measured ~26us combined).
// ---------------------------------------------------------------------------
constexpr int XBLOCKS = MDIM * KB;            // 262144 quant blocks
constexpr int XCTAS   = XBLOCKS / (8 * 4);    // 8192
constexpr int WCTAS   = 1024;

__global__ void quant_fused_kernel(const float* __restrict__ x,
                                   const float* __restrict__ w) {
    const int cta = blockIdx.x;
    if (cta < XCTAS) {
        const int warp = cta * 8 + (threadIdx.x >> 5);
        const int lane = threadIdx.x & 31;
        const size_t b0 = (size_t)warp * 4;

        float4 v4[4];
#pragma unroll
        for (int j = 0; j < 4; j++)
            v4[j] = ((const float4*)x)[(b0 + j) * 32 + lane];

        float v[4][4], amax[4];
#pragma unroll
        for (int j = 0; j < 4; j++) {
            v[j][0] = bf16_round(v4[j].x);
            v[j][1] = bf16_round(v4[j].y);
            v[j][2] = bf16_round(v4[j].z);
            v[j][3] = bf16_round(v4[j].w);
            amax[j] = fmaxf(fmaxf(fabsf(v[j][0]), fabsf(v[j][1])),
                            fmaxf(fabsf(v[j][2]), fabsf(v[j][3])));
        }
#pragma unroll
        for (int o = 16; o; o >>= 1) {
#pragma unroll
            for (int j = 0; j < 4; j++)
                amax[j] = fmaxf(amax[j], __shfl_xor_sync(0xffffffffu, amax[j], o));
        }
#pragma unroll
        for (int j = 0; j < 4; j++) {
            float s = fmaxf(amax[j], 1e-4f) / 448.0f;
            int e; float m = frexpf(s, &e);
            float s2 = (m == 0.5f) ? ldexpf(1.f, e - 1) : ldexpf(1.f, e);
            float inv = 1.f / s2;
            __nv_fp8x2_storage_t lo = __nv_cvt_float2_to_fp8x2(
                make_float2(v[j][0] * inv, v[j][1] * inv), __NV_SATFINITE, __NV_E4M3);
            __nv_fp8x2_storage_t hi = __nv_cvt_float2_to_fp8x2(
                make_float2(v[j][2] * inv, v[j][3] * inv), __NV_SATFINITE, __NV_E4M3);
            ((uint32_t*)g_x8)[(b0 + j) * 32 + lane] = (uint32_t)lo | ((uint32_t)hi << 16);
            if (lane == 0) g_sa[b0 + j] = s2;
        }
    } else {
        const int t = (cta - XCTAS) * 256 + threadIdx.x;
#pragma unroll
        for (int j = 0; j < 4; j++) {
            int i = t + j * (WCTAS * 256);
            float4 w4 = ((const float4*)w)[i];
            __nv_fp8x2_storage_t lo = __nv_cvt_float2_to_fp8x2(
                make_float2(w4.x, w4.y), __NV_SATFINITE, __NV_E4M3);
            __nv_fp8x2_storage_t hi = __nv_cvt_float2_to_fp8x2(
                make_float2(w4.z, w4.w), __NV_SATFINITE, __NV_E4M3);
            ((uint32_t*)g_w8)[i] = (uint32_t)lo | ((uint32_t)hi << 16);
        }
    }
}

// ---------------------------------------------------------------------------
// FP8 NT GEMM: CTA tile 64x64, 256 threads, 8 warps (4m x 2n), warp tile
// 16x32 (halved accumulators -> regs <= ~85 -> 3 CTAs/SM = 24 warps, 6/SMSP).
// 4-stage cp.async ring, ONE __syncthreads per k-block, ldmatrix.x4,
// two-level block-scale accumulation, hoisted addresses.
// ---------------------------------------------------------------------------
constexpr int BM = 64, BN = 64;
constexpr int STAGES = 4;
constexpr int ROWB = 128 + 16;                       // 144 B/row, conflict-free
constexpr int STAGE_BYTES = (BM + BN) * ROWB;        // 18432
constexpr int SMEM_TOTAL = STAGES * STAGE_BYTES;     // 73728 (3 CTAs -> 221 KB)

__device__ __forceinline__ void cp_async16(uint32_t dst, const void* src) {
    asm volatile("cp.async.cg.shared.global [%0], [%1], 16;\n" :: "r"(dst), "l"(src));
}
__device__ __forceinline__ void cp_commit() {
    asm volatile("cp.async.commit_group;\n" ::: "memory");
}
template <int N>
__device__ __forceinline__ void cp_wait() {
    asm volatile("cp.async.wait_group %0;\n" :: "n"(N) : "memory");
}
__device__ __forceinline__ void ldm_x4(uint32_t& r0, uint32_t& r1, uint32_t& r2, uint32_t& r3,
                                       uint32_t addr) {
    asm volatile("ldmatrix.sync.aligned.m8n8.x4.shared.b16 {%0,%1,%2,%3}, [%4];\n"
                 : "=r"(r0), "=r"(r1), "=r"(r2), "=r"(r3) : "r"(addr));
}
__device__ __forceinline__ void mma_fp8(float* c, const uint32_t* a, const uint32_t* b) {
    asm volatile("mma.sync.aligned.m16n8k32.row.col.f32.e4m3.e4m3.f32 "
                 "{%0,%1,%2,%3}, {%4,%5,%6,%7}, {%8,%9}, {%0,%1,%2,%3};\n"
                 : "+f"(c[0]), "+f"(c[1]), "+f"(c[2]), "+f"(c[3])
                 : "r"(a[0]), "r"(a[1]), "r"(a[2]), "r"(a[3]), "r"(b[0]), "r"(b[1]));
}

__global__ __launch_bounds__(256, 3) void gemm_kernel(float* __restrict__ C,
                                                      const float* __restrict__ sinv) {
    extern __shared__ uint8_t sm[];
    const int tid = threadIdx.x;
    const int lane = tid & 31;
    const int wid = tid >> 5;                 // 0..7
    const int bm = blockIdx.y * BM;
    const int bn = blockIdx.x * BN;
    const int wm = (wid & 3) * 16;            // 4 m-tiles of 16
    const int wn = (wid >> 2) * 32;           // 2 n-cols of 32

    const uint32_t sm_u32 = (uint32_t)__cvta_generic_to_shared(sm);

    // ---- per-thread loader pointers: 1024 chunks of 16B, 4 per thread ----
    const uint8_t* gsrc[4];
    uint32_t soff[4];
#pragma unroll
    for (int i = 0; i < 4; i++) {
        int c = tid + 256 * i;                // 0..1023
        if (c < BM * 8) {                     // A chunk
            int row = c >> 3, cc = c & 7;
            gsrc[i] = g_x8 + (size_t)(bm + row) * KDIM + cc * 16;
            soff[i] = (uint32_t)(row * ROWB + cc * 16);
        } else {                              // B chunk
            int cb = c - BM * 8;
            int row = cb >> 3, cc = cb & 7;
            gsrc[i] = g_w8 + (size_t)(bn + row) * KDIM + cc * 16;
            soff[i] = (uint32_t)(BM * ROWB + row * ROWB + cc * 16);
        }
    }
    auto load_stage = [&](int s, int kb) {
        uint32_t base = sm_u32 + (uint32_t)(s * STAGE_BYTES);
        uint32_t koff = (uint32_t)kb << 7;    // kb * 128 bytes
#pragma unroll
        for (int i = 0; i < 4; i++)
            cp_async16(base + soff[i], gsrc[i] + koff);
    };

    float master[4][4];
#pragma unroll
    for (int j = 0; j < 4; j++)
#pragma unroll
        for (int l = 0; l < 4; l++) master[j][l] = 0.f;

    load_stage(0, 0); cp_commit();
    load_stage(1, 1); cp_commit();
    load_stage(2, 2); cp_commit();

    // hoisted ldmatrix address components
    const int la_row  = lane & 15;
    const int la_half = lane >> 4;
    const int lb_row  = ((lane >> 4) << 3) + (lane & 7);
    const int lb_half = (lane >> 3) & 1;
    const uint32_t aBase = (uint32_t)((wm + la_row) * ROWB + la_half * 16);
    const uint32_t bBase0 = (uint32_t)(BM * ROWB + (wn + lb_row) * ROWB + lb_half * 16);
    const uint32_t bBase1 = bBase0 + 16u * ROWB;
    const int gr = lane >> 2;

    // scale pointers (hoisted)
    const float* psa0 = g_sa + (size_t)(bm + wm + gr) * KB;   // rows c0,c1
    const float* psa1 = psa0 + 8 * KB;                        // rows c2,c3
    const float* psw  = sinv + (size_t)(bn >> 7) * KB;

    for (int kb = 0; kb < KB; kb++) {
        int rem = KB - 1 - kb;
        if (rem >= 2)      cp_wait<2>();
        else if (rem == 1) cp_wait<1>();
        else               cp_wait<0>();
        __syncthreads();
        if (kb + 3 < KB) { load_stage((kb + 3) & 3, kb + 3); cp_commit(); }

        const uint32_t st = sm_u32 + (uint32_t)((kb & 3) * STAGE_BYTES);

        float part[4][4];
#pragma unroll
        for (int j = 0; j < 4; j++)
#pragma unroll
            for (int l = 0; l < 4; l++) part[j][l] = 0.f;

#pragma unroll
        for (int ks = 0; ks < 4; ks++) {      // four k32 steps in BK=128
            const uint32_t k0 = (uint32_t)(ks * 32);
            uint32_t a[4];
            ldm_x4(a[0], a[1], a[2], a[3], st + aBase + k0);
#pragma unroll
            for (int p = 0; p < 2; p++) {
                uint32_t b[4];
                ldm_x4(b[0], b[1], b[2], b[3],
                       st + (p ? bBase1 : bBase0) + k0);
                mma_fp8(part[2 * p + 0], a, b + 0);
                mma_fp8(part[2 * p + 1], a, b + 2);
            }
        }

        // ---- fold k-block scales into master ----
        float swk = __ldg(psw + kb);
        float f0 = __ldg(psa0 + kb) * swk;    // acc rows c0,c1
        float f1 = __ldg(psa1 + kb) * swk;    // acc rows c2,c3
#pragma unroll
        for (int nt = 0; nt < 4; nt++) {
            master[nt][0] += part[nt][0] * f0;
            master[nt][1] += part[nt][1] * f0;
            master[nt][2] += part[nt][2] * f1;
            master[nt][3] += part[nt][3] * f1;
        }
    }

    // ---- epilogue: round to bf16, store as fp32 (float2) ----
    const int gid = lane >> 2, tig = lane & 3;
#pragma unroll
    for (int nt = 0; nt < 4; nt++) {
        int row = bm + wm + gid;
        int col = bn + wn + nt * 8 + tig * 2;
        float2 v01 = make_float2(bf16_round(master[nt][0]), bf16_round(master[nt][1]));
        *(float2*)&C[(size_t)row * NDIM + col] = v01;
        float2 v23 = make_float2(bf16_round(master[nt][2]), bf16_round(master[nt][3]));
        *(float2*)&C[(size_t)(row + 8) * NDIM + col] = v23;
    }
}

// ---------------------------------------------------------------------------
// Inputs identified BY ELEMENT COUNT: x 33554432, weight 4194304, sinv 256.
// ---------------------------------------------------------------------------
extern "C" void kernel_launch(void* const* d_in, const int* in_sizes, int n_in,
                              void* d_out, int out_size) {
    const float* x = nullptr; const float* w = nullptr; const float* sinv = nullptr;
    for (int i = 0; i < n_in; i++) {
        long long sz = in_sizes[i];
        if (sz == (long long)MDIM * KDIM)      x    = (const float*)d_in[i];
        else if (sz == (long long)NDIM * KDIM) w    = (const float*)d_in[i];
        else                                   sinv = (const float*)d_in[i];
    }
    if (!x)    x    = (const float*)d_in[0];
    if (!w)    w    = (const float*)d_in[1];
    if (!sinv) sinv = (const float*)d_in[2];
    float* out = (float*)d_out;

    // 1) fused quantization (x + w in one launch)
    quant_fused_kernel<<<XCTAS + WCTAS, 256>>>(x, w);

    // 2) fp8 GEMM with per-block rescale, 3 CTAs/SM target
    cudaFuncSetAttribute(gemm_kernel, cudaFuncAttributeMaxDynamicSharedMemorySize, SMEM_TOTAL);
    dim3 grid(NDIM / BN, MDIM / BM);               // (32, 256)
    gemm_kernel<<<grid, 256, SMEM_TOTAL>>>(out, sinv);
}